// round 10
// baseline (speedup 1.0000x reference)
#include <cuda_runtime.h>
#include <cuda_bf16.h>
#include <cstdint>
#include <cstddef>

// Problem constants
#define Bq 4
#define Lq 128
#define Dq 128
#define Hq 8
#define Vq 32000
#define DHq (Dq*Hq)          // 1024
#define NEGC 1e9f
#define NROWS (Bq*Lq)        // 512
#define NSPLIT 37            // flash grid = 37*4 = 148 blocks
#define VUNITS32 1000        // Vq/32
#define GPARTS 32            // G1: 16 (k*8+sk) + G2: 16 (k*8+c)

// ---------------- scratch (device globals) ----------------
__device__ float g_meanE_part[128*128];
__device__ float g_meanE[Dq];
__device__ float g_qz[NROWS*Dq];
__device__ float g_t1[Bq*2*Lq*DHq];              // [z][k][i][(b*H+c)]
__device__ float g_F[Bq*2*Hq*Lq*Lq];             // [z][k][c][i][j]
__device__ float g_Hm[2*Bq*Hq*Lq*Lq];            // [k][z][c][i][j]
__device__ float g_s1[Bq*2*Lq*DHq];
__device__ float g_Gpart[(size_t)GPARTS*NROWS*Dq];
__device__ float g_Um[(size_t)NSPLIT*NROWS*Dq];  // flash partial accumulators
__device__ float g_srow[NSPLIT*NROWS];

// ---------------- mma helpers ----------------
__device__ __forceinline__ uint32_t f2tf(float f){
    uint32_t u; asm("cvt.rna.tf32.f32 %0, %1;" : "=r"(u) : "f"(f)); return u;
}
__device__ __forceinline__ void mma8(float c[4], const uint32_t a[4], const uint32_t b[2]){
    asm("mma.sync.aligned.m16n8k8.row.col.f32.tf32.tf32.f32 "
        "{%0,%1,%2,%3},{%4,%5,%6,%7},{%8,%9},{%0,%1,%2,%3};"
        : "+f"(c[0]),"+f"(c[1]),"+f"(c[2]),"+f"(c[3])
        : "r"(a[0]),"r"(a[1]),"r"(a[2]),"r"(a[3]),"r"(b[0]),"r"(b[1]));
}

// ---------------- small kernels ----------------
__global__ void k_meanE_part(const float* __restrict__ E){
    int b = blockIdx.x, t = threadIdx.x;
    float s = 0.f;
    int v0 = b * (Vq/128);
    for (int v = 0; v < Vq/128; v++) s += E[(size_t)(v0+v)*Dq + t];
    g_meanE_part[b*128 + t] = s;
}
__global__ void k_meanE_red(){
    int t = threadIdx.x;
    float s = 0.f;
    for (int b = 0; b < 128; b++) s += g_meanE_part[b*128 + t];
    g_meanE[t] = s / (float)Vq;
}

__global__ void k_hsoftmax(const int* __restrict__ mask){
    int bi = blockIdx.x;                    // z*H*L + c*L + i
    int i = bi & (Lq-1);
    int c = (bi >> 7) & (Hq-1);
    int z = bi >> 10;
    int j = threadIdx.x;
    bool mok = (mask[z*Lq+i] != 0) && (mask[z*Lq+j] != 0);
    float v;
    if (!mok || j == i) v = -NEGC;
    else if (j > i) v = g_F[((((size_t)z*2+0)*Hq+c)*Lq+i)*Lq + j];
    else            v = g_F[((((size_t)z*2+1)*Hq+c)*Lq+i)*Lq + j];
    __shared__ float r1[4], r2[4];
    float m = v;
    #pragma unroll
    for (int o = 16; o; o >>= 1) m = fmaxf(m, __shfl_xor_sync(0xffffffffu, m, o));
    if ((j&31)==0) r1[j>>5] = m;
    __syncthreads();
    m = fmaxf(fmaxf(r1[0],r1[1]), fmaxf(r1[2],r1[3]));
    float e = __expf(v - m);
    float s = e;
    #pragma unroll
    for (int o = 16; o; o >>= 1) s += __shfl_xor_sync(0xffffffffu, s, o);
    if ((j&31)==0) r2[j>>5] = s;
    __syncthreads();
    s = r2[0]+r2[1]+r2[2]+r2[3];
    float p = e/s;
    size_t o0 = ((((size_t)0*Bq+z)*Hq+c)*Lq+i)*Lq + j;
    size_t o1 = ((((size_t)1*Bq+z)*Hq+c)*Lq+i)*Lq + j;
    g_Hm[o0] = (j > i) ? p : 0.f;
    g_Hm[o1] = (j < i) ? p : 0.f;
}

// fused per-row: [G partial reduce] + [flash combine or meanE] + compose + Z-softmax
__global__ void k_fuse_row(const int* __restrict__ mask, const float* __restrict__ x,
                           const int* __restrict__ m_mask, int mode, int addG){
    int row = blockIdx.x, d = threadIdx.x;
    __shared__ float ss[NSPLIT];
    __shared__ float r1[4], r2[4];

    float Gv = 0.f;
    if (addG){
        #pragma unroll 8
        for (int p = 0; p < GPARTS; p++) Gv += g_Gpart[((size_t)p*NROWS + row)*Dq + d];
    }

    float u;
    if (mode){
        if (d < NSPLIT) ss[d] = g_srow[d*NROWS + row];
        __syncthreads();
        float S = 0.f, Uv = 0.f;
        for (int sp = 0; sp < NSPLIT; sp++){
            S  += ss[sp];
            Uv += g_Um[((size_t)sp*NROWS + row)*Dq + d];
        }
        u = Uv / S;
    } else {
        u = g_meanE[d];
    }
    float mm = (float)m_mask[row];
    float v = x[row*Dq + d]*(1.f - mm) + u*mm + Gv;

    float m = v;
    #pragma unroll
    for (int o = 16; o; o >>= 1) m = fmaxf(m, __shfl_xor_sync(0xffffffffu, m, o));
    if ((d&31)==0) r1[d>>5] = m;
    __syncthreads();
    m = fmaxf(fmaxf(r1[0],r1[1]), fmaxf(r1[2],r1[3]));
    float e = __expf(v - m);
    float s = e;
    #pragma unroll
    for (int o = 16; o; o >>= 1) s += __shfl_xor_sync(0xffffffffu, s, o);
    if ((d&31)==0) r2[d>>5] = s;
    __syncthreads();
    s = r2[0]+r2[1]+r2[2]+r2[3];
    float keep = (mask[row] != 0) ? 1.f : 0.f;
    g_qz[row*Dq + d] = e/s*keep;
}

// ---------------- fused flash V kernel ----------------
// 128-row q blocks; 8 warps = 4 row-slabs (32 rows) x 2 col halves.
// E tile shrunk to 32 V-rows per chunk -> real smem 104 KB; we REQUEST 120 KB so
// only 1 flash block/SM but a 100 KB GEMM block can co-reside (overlap streams).
#define QZW (128*132)
#define FEW (32*132)
#define FPW (128*36)
#define FLASH_SMEM_REQ (120*1024)

__global__ void __launch_bounds__(256,2) k_flash(const float* __restrict__ E){
    extern __shared__ uint32_t sh[];
    uint32_t* qz_s = sh;            // [128][132]
    uint32_t* E_s  = sh + QZW;      // [32][132]
    uint32_t* p_s  = E_s + FEW;     // [128][36]
    float* wred = (float*)(p_s + FPW);  // [2][128]

    int tid = threadIdx.x;
    int sp = blockIdx.x, by = blockIdx.y;     // by in 0..3
    int warp = tid>>5, lane = tid&31;
    int wm = warp>>1, wn = warp&1;
    int g = lane>>2, q = lane&3;

    // stage full qz block (128x128)
    {
        const float* A = &g_qz[(by*128)*Dq];
        #pragma unroll
        for (int it = 0; it < 16; it++){
            int i4 = tid + it*256;
            int r = i4 >> 5, c4 = (i4 & 31)*4;
            float4 v = *(const float4*)&A[r*Dq + c4];
            *(uint4*)&qz_s[r*132+c4] = make_uint4(f2tf(v.x),f2tf(v.y),f2tf(v.z),f2tf(v.w));
        }
    }

    float Ua[2][8][4];
    #pragma unroll
    for (int s_ = 0; s_ < 2; s_++)
        #pragma unroll
        for (int i = 0; i < 8; i++){ Ua[s_][i][0]=0;Ua[s_][i][1]=0;Ua[s_][i][2]=0;Ua[s_][i][3]=0; }
    float s00=0.f, s01=0.f, s10=0.f, s11=0.f;

    int rA = wm*32 + g;
    int rB = rA + 16;

    int cu0 = (sp*VUNITS32)/NSPLIT, cu1 = ((sp+1)*VUNITS32)/NSPLIT;
    for (int ci = cu0; ci < cu1; ci++){
        __syncthreads();   // prior MMA2 done with E_s / p_s
        const float* Eb = &E[(size_t)ci*32*Dq];
        #pragma unroll
        for (int it = 0; it < 4; it++){
            int i4 = tid + it*256;
            int r = i4 >> 5, c4 = (i4 & 31)*4;
            float4 v = *(const float4*)&Eb[r*Dq + c4];
            *(uint4*)&E_s[r*132+c4] = make_uint4(f2tf(v.x),f2tf(v.y),f2tf(v.z),f2tf(v.w));
        }
        __syncthreads();

        // MMA1: L[32 rows x 16 cols per warp] = qz @ E^T
        float L[2][2][4];
        #pragma unroll
        for (int s_ = 0; s_ < 2; s_++)
            #pragma unroll
            for (int i = 0; i < 2; i++){ L[s_][i][0]=0;L[s_][i][1]=0;L[s_][i][2]=0;L[s_][i][3]=0; }
        const uint32_t* qr0 = &qz_s[rA*132 + q];
        const uint32_t* qr1 = &qz_s[rB*132 + q];
        #pragma unroll
        for (int ks = 0; ks < 16; ks++){
            int kb = ks*8;
            uint32_t a0[4] = { qr0[kb], qr0[kb + 8*132], qr0[kb+4], qr0[kb+4 + 8*132] };
            uint32_t a1[4] = { qr1[kb], qr1[kb + 8*132], qr1[kb+4], qr1[kb+4 + 8*132] };
            #pragma unroll
            for (int nt = 0; nt < 2; nt++){
                int nc = wn*16 + nt*8 + g;
                uint32_t b[2] = { E_s[nc*132 + kb + q], E_s[nc*132 + kb + q + 4] };
                mma8(L[0][nt], a0, b);
                mma8(L[1][nt], a1, b);
            }
        }

        // p = exp(L) (|L| <= ~6: qz rows are prob. distributions, E ~ N(0,1))
        #pragma unroll
        for (int nt = 0; nt < 2; nt++){
            int c0 = wn*16 + nt*8 + 2*q;
            float p0 = __expf(L[0][nt][0]), p1 = __expf(L[0][nt][1]);
            float p2 = __expf(L[0][nt][2]), p3 = __expf(L[0][nt][3]);
            s00 += p0 + p1; s01 += p2 + p3;
            p_s[rA*36 + c0] = f2tf(p0);     p_s[rA*36 + c0 + 1] = f2tf(p1);
            p_s[(rA+8)*36 + c0] = f2tf(p2); p_s[(rA+8)*36 + c0 + 1] = f2tf(p3);
            float u0 = __expf(L[1][nt][0]), u1 = __expf(L[1][nt][1]);
            float u2 = __expf(L[1][nt][2]), u3 = __expf(L[1][nt][3]);
            s10 += u0 + u1; s11 += u2 + u3;
            p_s[rB*36 + c0] = f2tf(u0);     p_s[rB*36 + c0 + 1] = f2tf(u1);
            p_s[(rB+8)*36 + c0] = f2tf(u2); p_s[(rB+8)*36 + c0 + 1] = f2tf(u3);
        }
        __syncthreads();

        // MMA2: Ua[32x128 per warp] += p @ E   (K = 32)
        #pragma unroll
        for (int ks = 0; ks < 4; ks++){
            int kb = ks*8;
            uint32_t a0[4] = { p_s[rA*36 + kb + q],     p_s[(rA+8)*36 + kb + q],
                               p_s[rA*36 + kb + q + 4], p_s[(rA+8)*36 + kb + q + 4] };
            uint32_t a1[4] = { p_s[rB*36 + kb + q],     p_s[(rB+8)*36 + kb + q],
                               p_s[rB*36 + kb + q + 4], p_s[(rB+8)*36 + kb + q + 4] };
            #pragma unroll
            for (int nt2 = 0; nt2 < 8; nt2++){
                int nd = wn*64 + nt2*8 + g;
                uint32_t b[2] = { E_s[(kb+q)*132 + nd], E_s[(kb+q+4)*132 + nd] };
                mma8(Ua[0][nt2], a0, b);
                mma8(Ua[1][nt2], a1, b);
            }
        }
    }

    size_t base = ((size_t)sp*NROWS + by*128);
    #pragma unroll
    for (int s_ = 0; s_ < 2; s_++){
        int rlo = (s_ ? rB : rA), rhi = rlo + 8;
        #pragma unroll
        for (int nt2 = 0; nt2 < 8; nt2++){
            int col = wn*64 + nt2*8 + 2*q;
            *(float2*)&g_Um[(base + rlo)*Dq + col] = make_float2(Ua[s_][nt2][0], Ua[s_][nt2][1]);
            *(float2*)&g_Um[(base + rhi)*Dq + col] = make_float2(Ua[s_][nt2][2], Ua[s_][nt2][3]);
        }
    }
    #pragma unroll
    for (int o = 1; o <= 2; o <<= 1){
        s00 += __shfl_xor_sync(0xffffffffu, s00, o);
        s01 += __shfl_xor_sync(0xffffffffu, s01, o);
        s10 += __shfl_xor_sync(0xffffffffu, s10, o);
        s11 += __shfl_xor_sync(0xffffffffu, s11, o);
    }
    if (q == 0){
        wred[wn*128 + rA]     = s00;
        wred[wn*128 + rA + 8] = s01;
        wred[wn*128 + rB]     = s10;
        wred[wn*128 + rB + 8] = s11;
    }
    __syncthreads();
    if (tid < 128)
        g_srow[sp*NROWS + by*128 + tid] = wred[tid] + wred[128+tid];
}

// final logits: out[512,32000] = qz @ E^T — 128-row blocks, 32x32 warp tiles
#define LEW (64*132)
#define LOGIT_SMEM ((QZW + LEW)*4)
__global__ void __launch_bounds__(256,1) k_logits(const float* __restrict__ E, float* __restrict__ out){
    extern __shared__ uint32_t sh[];
    uint32_t* qz_s = sh;          // [128][132]
    uint32_t* E_s  = sh + QZW;    // [64][132]
    int tid = threadIdx.x;
    int bx = blockIdx.x, by = blockIdx.y;
    int warp = tid>>5, lane = tid&31;
    int wm = warp>>1, wn = warp&1;
    int g = lane>>2, q = lane&3;
    {
        const float* A = &g_qz[(by*128)*Dq];
        #pragma unroll
        for (int it = 0; it < 16; it++){
            int i4 = tid + it*256;
            int r = i4 >> 5, c4 = (i4 & 31)*4;
            float4 v = *(const float4*)&A[r*Dq + c4];
            *(uint4*)&qz_s[r*132+c4] = make_uint4(f2tf(v.x),f2tf(v.y),f2tf(v.z),f2tf(v.w));
        }
        const float* Eb = &E[(size_t)(bx*64)*Dq];
        #pragma unroll
        for (int it = 0; it < 8; it++){
            int i4 = tid + it*256;
            int r = i4 >> 5, c4 = (i4 & 31)*4;
            float4 e = *(const float4*)&Eb[r*Dq + c4];
            *(uint4*)&E_s[r*132+c4] = make_uint4(f2tf(e.x),f2tf(e.y),f2tf(e.z),f2tf(e.w));
        }
    }
    __syncthreads();
    int rA = wm*32 + g, rB = rA + 16;
    float L[2][4][4];
    #pragma unroll
    for (int s_ = 0; s_ < 2; s_++)
        #pragma unroll
        for (int i = 0; i < 4; i++){ L[s_][i][0]=0;L[s_][i][1]=0;L[s_][i][2]=0;L[s_][i][3]=0; }
    const uint32_t* qr0 = &qz_s[rA*132 + q];
    const uint32_t* qr1 = &qz_s[rB*132 + q];
    #pragma unroll
    for (int ks = 0; ks < 16; ks++){
        int kb = ks*8;
        uint32_t a0[4] = { qr0[kb], qr0[kb + 8*132], qr0[kb+4], qr0[kb+4 + 8*132] };
        uint32_t a1[4] = { qr1[kb], qr1[kb + 8*132], qr1[kb+4], qr1[kb+4 + 8*132] };
        #pragma unroll
        for (int nt = 0; nt < 4; nt++){
            int nc = wn*32 + nt*8 + g;
            uint32_t b[2] = { E_s[nc*132 + kb + q], E_s[nc*132 + kb + q + 4] };
            mma8(L[0][nt], a0, b);
            mma8(L[1][nt], a1, b);
        }
    }
    #pragma unroll
    for (int s_ = 0; s_ < 2; s_++){
        int rlo = by*128 + (s_ ? rB : rA), rhi = rlo + 8;
        #pragma unroll
        for (int nt = 0; nt < 4; nt++){
            int col = bx*64 + wn*32 + nt*8 + 2*q;
            *(float2*)&out[(size_t)rlo*Vq + col] = make_float2(L[s_][nt][0], L[s_][nt][1]);
            *(float2*)&out[(size_t)rhi*Vq + col] = make_float2(L[s_][nt][2], L[s_][nt][3]);
        }
    }
}

// ---------------- generic strided batched tf32 GEMM ----------------
// M=128 (always full), N-tile 64, K=128. 8 warps = 4 row-slabs(32) x 2 col(32).
// aMode/bMode: 0 = scalar mn-fast, 1 = scalar k-fast, 2 = float4 (contiguous) path.
struct GCfg {
    const float* A; const float* B; float* C;
    int sAi, sAk, sBk, sBj, sCi, sCj;
    int b3, b2;
    int aB1, aB2, aB3, bB1, bB2, bB3, cB1, cB2, cB3;
    int aMode, bMode;
};

#define GEMM_SMEM ((128*132 + 128*68)*4)   // 102400 B

__device__ __forceinline__ void gemm_body(const GCfg& c, int bz, uint32_t* dsh){
    uint32_t* As = dsh;             // [128][132]  m-major
    uint32_t* Bs = dsh + 128*132;   // [128][68]   k-major

    int i3 = bz % c.b3; int t_ = bz / c.b3; int i2 = t_ % c.b2; int i1 = t_ / c.b2;
    const float* A  = c.A + (size_t)i1*c.aB1 + (size_t)i2*c.aB2 + (size_t)i3*c.aB3;
    const float* Bm = c.B + (size_t)i1*c.bB1 + (size_t)i2*c.bB2 + (size_t)i3*c.bB3;
    float* C        = c.C + (size_t)i1*c.cB1 + (size_t)i2*c.cB2 + (size_t)i3*c.cB3;
    int n0 = blockIdx.x*64;

    int tid = threadIdx.x;
    int warp = tid>>5, lane = tid&31;
    int wm = warp>>1, wn = warp&1;
    int g = lane>>2, q = lane&3;

    // ---- stage A: 128 x 128 ----
    if (c.aMode == 2){
        #pragma unroll
        for (int it = 0; it < 16; it++){
            int i4 = tid + it*256;
            int r = i4 >> 5, k4 = (i4 & 31)*4;
            float4 v = *(const float4*)&A[(size_t)r*c.sAi + k4];
            *(uint4*)&As[r*132 + k4] = make_uint4(f2tf(v.x),f2tf(v.y),f2tf(v.z),f2tf(v.w));
        }
    } else if (c.aMode == 1){
        #pragma unroll
        for (int it = 0; it < 64; it++){
            int idx = tid + it*256;
            int kk = idx & 127, mn = idx >> 7;
            As[mn*132 + kk] = f2tf(A[(size_t)mn*c.sAi + (size_t)kk*c.sAk]);
        }
    } else {
        #pragma unroll
        for (int it = 0; it < 64; it++){
            int idx = tid + it*256;
            int mn = idx & 127, kk = idx >> 7;
            As[mn*132 + kk] = f2tf(A[(size_t)mn*c.sAi + (size_t)kk*c.sAk]);
        }
    }
    // ---- stage B: 128k x 64n ----
    if (c.bMode == 2){
        #pragma unroll
        for (int it = 0; it < 8; it++){
            int i4 = tid + it*256;
            int kk = i4 >> 4, n4 = (i4 & 15)*4;
            float4 v = *(const float4*)&Bm[(size_t)kk*c.sBk + (n0+n4)];
            *(uint4*)&Bs[kk*68 + n4] = make_uint4(f2tf(v.x),f2tf(v.y),f2tf(v.z),f2tf(v.w));
        }
    } else if (c.bMode == 1){
        #pragma unroll
        for (int it = 0; it < 32; it++){
            int idx = tid + it*256;
            int kk = idx & 127, mn = idx >> 7;
            Bs[kk*68 + mn] = f2tf(Bm[(size_t)kk*c.sBk + (size_t)(n0+mn)*c.sBj]);
        }
    } else {
        #pragma unroll
        for (int it = 0; it < 32; it++){
            int idx = tid + it*256;
            int mn = idx & 63, kk = idx >> 6;
            Bs[kk*68 + mn] = f2tf(Bm[(size_t)kk*c.sBk + (size_t)(n0+mn)*c.sBj]);
        }
    }
    __syncthreads();

    float acc[2][4][4];
    #pragma unroll
    for (int s_ = 0; s_ < 2; s_++)
        #pragma unroll
        for (int i = 0; i < 4; i++){ acc[s_][i][0]=0;acc[s_][i][1]=0;acc[s_][i][2]=0;acc[s_][i][3]=0; }

    int rA = wm*32 + g, rB = rA + 16;
    const uint32_t* a0p = &As[rA*132 + q];
    const uint32_t* a1p = &As[rB*132 + q];
    #pragma unroll
    for (int ks = 0; ks < 16; ks++){
        int kb = ks*8;
        uint32_t a0[4] = { a0p[kb], a0p[kb + 8*132], a0p[kb+4], a0p[kb+4 + 8*132] };
        uint32_t a1[4] = { a1p[kb], a1p[kb + 8*132], a1p[kb+4], a1p[kb+4 + 8*132] };
        #pragma unroll
        for (int nt = 0; nt < 4; nt++){
            int n = wn*32 + nt*8 + g;
            uint32_t b[2] = { Bs[(kb+q)*68 + n], Bs[(kb+q+4)*68 + n] };
            mma8(acc[0][nt], a0, b);
            mma8(acc[1][nt], a1, b);
        }
    }

    #pragma unroll
    for (int s_ = 0; s_ < 2; s_++){
        int rlo = (s_ ? rB : rA), rhi = rlo + 8;
        #pragma unroll
        for (int nt = 0; nt < 4; nt++){
            int c0 = n0 + wn*32 + nt*8 + 2*q;
            C[(size_t)rlo*c.sCi + (size_t)(c0  )*c.sCj] = acc[s_][nt][0];
            C[(size_t)rlo*c.sCi + (size_t)(c0+1)*c.sCj] = acc[s_][nt][1];
            C[(size_t)rhi*c.sCi + (size_t)(c0  )*c.sCj] = acc[s_][nt][2];
            C[(size_t)rhi*c.sCi + (size_t)(c0+1)*c.sCj] = acc[s_][nt][3];
        }
    }
}

__global__ void __launch_bounds__(256,2) k_gemm_tf(GCfg c){
    extern __shared__ uint32_t dsh[];
    gemm_body(c, blockIdx.z, dsh);
}

__global__ void __launch_bounds__(256,2) k_gemm_dual(GCfg c0, GCfg c1, int zsplit){
    extern __shared__ uint32_t dsh[];
    int bz = blockIdx.z;
    if (bz < zsplit) gemm_body(c0, bz, dsh);
    else             gemm_body(c1, bz - zsplit, dsh);
}

// ---------------- host ----------------
extern "C" void kernel_launch(void* const* d_in, const int* in_sizes, int n_in,
                              void* d_out, int out_size){
    const float* x      = (const float*)d_in[0];
    const int*   mask   = (const int*)  d_in[1];
    const float* E      = (const float*)d_in[2];
    const int*   m_mask = (const int*)  d_in[3];
    const float* T      = (const float*)d_in[4];
    float* out = (float*)d_out;

    // one-time side stream + fork/join events (no device memory involved)
    static cudaStream_t s2 = nullptr;
    static cudaEvent_t evA = nullptr, evB = nullptr;
    if (s2 == nullptr){
        cudaStreamCreateWithFlags(&s2, cudaStreamNonBlocking);
        cudaEventCreateWithFlags(&evA, cudaEventDisableTiming);
        cudaEventCreateWithFlags(&evB, cudaEventDisableTiming);
    }

    cudaFuncSetAttribute(k_flash,    cudaFuncAttributeMaxDynamicSharedMemorySize, FLASH_SMEM_REQ);
    cudaFuncSetAttribute(k_logits,   cudaFuncAttributeMaxDynamicSharedMemorySize, LOGIT_SMEM);
    cudaFuncSetAttribute(k_gemm_tf,  cudaFuncAttributeMaxDynamicSharedMemorySize, GEMM_SMEM);
    cudaFuncSetAttribute(k_gemm_dual,cudaFuncAttributeMaxDynamicSharedMemorySize, GEMM_SMEM);

    void* qp;
    float *Pqz,*Pt1,*PF,*PHm,*Ps1,*PGp;
    cudaGetSymbolAddress(&qp, g_qz);    Pqz = (float*)qp;
    cudaGetSymbolAddress(&qp, g_t1);    Pt1 = (float*)qp;
    cudaGetSymbolAddress(&qp, g_F);     PF  = (float*)qp;
    cudaGetSymbolAddress(&qp, g_Hm);    PHm = (float*)qp;
    cudaGetSymbolAddress(&qp, g_s1);    Ps1 = (float*)qp;
    cudaGetSymbolAddress(&qp, g_Gpart); PGp = (float*)qp;

    // --- GEMM configs (M=128 full tile, N-tile 64) ---
    GCfg cT1 = { Pqz, T, Pt1,
        Dq,1,  DHq,1,  DHq,1,
        1,2,
        Lq*Dq,0,0,   0,Dq*DHq,0,   2*Lq*DHq,Lq*DHq,0,
        2,2 };
    GCfg cF = { Pt1, Pqz, PF,
        DHq,Hq,  1,Dq,  Lq,1,
        8,2,
        2*Lq*DHq,Lq*DHq,1,  Lq*Dq,0,0,  2*Hq*Lq*Lq,Hq*Lq*Lq,Lq*Lq,
        1,1 };
    GCfg cS1 = { PHm, Pqz, Ps1,
        Lq,1,  Dq,1,  DHq,Hq,
        8,2,
        Hq*Lq*Lq, Bq*Hq*Lq*Lq, Lq*Lq,   Lq*Dq,0,0,   2*Lq*DHq,Lq*DHq,1,
        2,2 };
    GCfg cG2 = { PHm, Pt1, PGp + (size_t)16*NROWS*Dq,
        1,Lq,  DHq,Hq,  Dq,1,
        8,2,
        Hq*Lq*Lq, Bq*Hq*Lq*Lq, Lq*Lq,
        2*Lq*DHq, Lq*DHq,      1,
        Lq*Dq,    8*NROWS*Dq,  NROWS*Dq,
        0,0 };
    GCfg cG1 = { Ps1, T, PGp,
        DHq,1,  1,DHq,  Dq,1,
        8,2,
        2*Lq*DHq, Lq*DHq, 128,
        0,        Dq*DHq, 128,
        Lq*Dq,    8*NROWS*Dq, NROWS*Dq,
        2,1 };

    // preprocessing: meanE, then initial compose+softmax (fuse_row, no G, meanE mode)
    k_meanE_part<<<128,128>>>(E);
    k_meanE_red<<<1,128>>>();
    k_fuse_row<<<NROWS, 128>>>(mask, x, m_mask, 0, 0);

    for (int t = 0; t < 4; t++){
        if (t > 0){
            // fork: flash depends only on qz (written by previous fuse_row)
            cudaEventRecord(evA, 0);
            cudaStreamWaitEvent(s2, evA, 0);
            k_flash<<<dim3(NSPLIT, 4), 256, FLASH_SMEM_REQ, s2>>>(E);
            cudaEventRecord(evB, s2);
        }

        k_gemm_tf<<<dim3(16,1,8),  256, GEMM_SMEM>>>(cT1);
        k_gemm_tf<<<dim3(2,1,64),  256, GEMM_SMEM>>>(cF);
        k_hsoftmax<<<Bq*Hq*Lq, 128>>>(mask);
        k_gemm_dual<<<dim3(2,1,128), 256, GEMM_SMEM>>>(cS1, cG2, 64);
        k_gemm_tf<<<dim3(2,1,64),  256, GEMM_SMEM>>>(cG1);

        if (t > 0){
            // join: fuse_row needs flash partials
            cudaStreamWaitEvent(0, evB, 0);
        }
        k_fuse_row<<<NROWS, 128>>>(mask, x, m_mask, (t > 0) ? 1 : 0, 1);

        if (t == 3){
            k_logits<<<dim3(Vq/64, 4), 256, LOGIT_SMEM>>>(E, out);
        }
    }
}

// round 14
// speedup vs baseline: 1.0545x; 1.0545x over previous
#include <cuda_runtime.h>
#include <cuda_bf16.h>
#include <cstdint>
#include <cstddef>

// Problem constants
#define Bq 4
#define Lq 128
#define Dq 128
#define Hq 8
#define Vq 32000
#define DHq (Dq*Hq)          // 1024
#define NEGC 1e9f
#define NROWS (Bq*Lq)        // 512
#define NSPLIT 37            // flash grid = 37*4 = 148 blocks = 1 wave
#define VUNITS 500           // Vq/64
#define GPARTS 32            // G1: 16 (k*8+c) + G2: 16 (k*8+c)

// ---------------- scratch (device globals) ----------------
__device__ float g_meanE_part[128*128];
__device__ float g_meanE[Dq];
__device__ float g_qz[NROWS*Dq];
__device__ float g_t1[Bq*2*Lq*DHq];              // [z][k][i][(b*H+c)]
__device__ float g_t2[Bq*2*Lq*DHq];              // [z][k][j][(a*H+c)]
__device__ float g_F[Bq*2*Hq*Lq*Lq];             // [z][k][c][i][j]
__device__ float g_Hm[2*Bq*Hq*Lq*Lq];            // [k][z][c][i][j]
__device__ float g_Gpart[(size_t)GPARTS*NROWS*Dq];
__device__ float g_Um[(size_t)NSPLIT*NROWS*Dq];  // flash partial accumulators
__device__ float g_srow[NSPLIT*NROWS];

// ---------------- mma helpers ----------------
__device__ __forceinline__ uint32_t f2tf(float f){
    uint32_t u; asm("cvt.rna.tf32.f32 %0, %1;" : "=r"(u) : "f"(f)); return u;
}
__device__ __forceinline__ void mma8(float c[4], const uint32_t a[4], const uint32_t b[2]){
    asm("mma.sync.aligned.m16n8k8.row.col.f32.tf32.tf32.f32 "
        "{%0,%1,%2,%3},{%4,%5,%6,%7},{%8,%9},{%0,%1,%2,%3};"
        : "+f"(c[0]),"+f"(c[1]),"+f"(c[2]),"+f"(c[3])
        : "r"(a[0]),"r"(a[1]),"r"(a[2]),"r"(a[3]),"r"(b[0]),"r"(b[1]));
}

// ---------------- small kernels ----------------
__global__ void k_meanE_part(const float* __restrict__ E){
    int b = blockIdx.x, t = threadIdx.x;
    float s = 0.f;
    int v0 = b * (Vq/128);
    for (int v = 0; v < Vq/128; v++) s += E[(size_t)(v0+v)*Dq + t];
    g_meanE_part[b*128 + t] = s;
}
__global__ void k_meanE_red(){
    int t = threadIdx.x;
    float s = 0.f;
    for (int b = 0; b < 128; b++) s += g_meanE_part[b*128 + t];
    g_meanE[t] = s / (float)Vq;
}

__global__ void k_hsoftmax(const int* __restrict__ mask){
    int bi = blockIdx.x;                    // z*H*L + c*L + i
    int i = bi & (Lq-1);
    int c = (bi >> 7) & (Hq-1);
    int z = bi >> 10;
    int j = threadIdx.x;
    bool mok = (mask[z*Lq+i] != 0) && (mask[z*Lq+j] != 0);
    float v;
    if (!mok || j == i) v = -NEGC;
    else if (j > i) v = g_F[((((size_t)z*2+0)*Hq+c)*Lq+i)*Lq + j];
    else            v = g_F[((((size_t)z*2+1)*Hq+c)*Lq+i)*Lq + j];
    __shared__ float r1[4], r2[4];
    float m = v;
    #pragma unroll
    for (int o = 16; o; o >>= 1) m = fmaxf(m, __shfl_xor_sync(0xffffffffu, m, o));
    if ((j&31)==0) r1[j>>5] = m;
    __syncthreads();
    m = fmaxf(fmaxf(r1[0],r1[1]), fmaxf(r1[2],r1[3]));
    float e = __expf(v - m);
    float s = e;
    #pragma unroll
    for (int o = 16; o; o >>= 1) s += __shfl_xor_sync(0xffffffffu, s, o);
    if ((j&31)==0) r2[j>>5] = s;
    __syncthreads();
    s = r2[0]+r2[1]+r2[2]+r2[3];
    float p = e/s;
    size_t o0 = ((((size_t)0*Bq+z)*Hq+c)*Lq+i)*Lq + j;
    size_t o1 = ((((size_t)1*Bq+z)*Hq+c)*Lq+i)*Lq + j;
    g_Hm[o0] = (j > i) ? p : 0.f;
    g_Hm[o1] = (j < i) ? p : 0.f;
}

// fused per-row: [G partial reduce] + [flash combine or meanE] + compose + Z-softmax
__global__ void k_fuse_row(const int* __restrict__ mask, const float* __restrict__ x,
                           const int* __restrict__ m_mask, int mode, int addG){
    int row = blockIdx.x, d = threadIdx.x;
    __shared__ float ss[NSPLIT];
    __shared__ float r1[4], r2[4];

    float Gv = 0.f;
    if (addG){
        #pragma unroll 8
        for (int p = 0; p < GPARTS; p++) Gv += g_Gpart[((size_t)p*NROWS + row)*Dq + d];
    }

    float u;
    if (mode){
        if (d < NSPLIT) ss[d] = g_srow[d*NROWS + row];
        __syncthreads();
        float S = 0.f, Uv = 0.f;
        for (int sp = 0; sp < NSPLIT; sp++){
            S  += ss[sp];
            Uv += g_Um[((size_t)sp*NROWS + row)*Dq + d];
        }
        u = Uv / S;
    } else {
        u = g_meanE[d];
    }
    float mm = (float)m_mask[row];
    float v = x[row*Dq + d]*(1.f - mm) + u*mm + Gv;

    float m = v;
    #pragma unroll
    for (int o = 16; o; o >>= 1) m = fmaxf(m, __shfl_xor_sync(0xffffffffu, m, o));
    if ((d&31)==0) r1[d>>5] = m;
    __syncthreads();
    m = fmaxf(fmaxf(r1[0],r1[1]), fmaxf(r1[2],r1[3]));
    float e = __expf(v - m);
    float s = e;
    #pragma unroll
    for (int o = 16; o; o >>= 1) s += __shfl_xor_sync(0xffffffffu, s, o);
    if ((d&31)==0) r2[d>>5] = s;
    __syncthreads();
    s = r2[0]+r2[1]+r2[2]+r2[3];
    float keep = (mask[row] != 0) ? 1.f : 0.f;
    g_qz[row*Dq + d] = e/s*keep;
}

// ---------------- fused flash V kernel (round-9 proven shape) ----------------
// 128-row q blocks; 8 warps = 4 row-slabs (32 rows) x 2 col halves; 64-row E chunks.
#define QZW (128*132)
#define EW  (64*132)
#define PW  (128*68)
#define FLASH_SMEM ((QZW + EW + PW + 256)*4)

__global__ void __launch_bounds__(256,1) k_flash(const float* __restrict__ E){
    extern __shared__ uint32_t sh[];
    uint32_t* qz_s = sh;           // [128][132]
    uint32_t* E_s  = sh + QZW;     // [64][132]
    uint32_t* p_s  = E_s + EW;     // [128][68]
    float* wred = (float*)(p_s + PW);  // [2][128]

    int tid = threadIdx.x;
    int sp = blockIdx.x, by = blockIdx.y;     // by in 0..3
    int warp = tid>>5, lane = tid&31;
    int wm = warp>>1, wn = warp&1;
    int g = lane>>2, q = lane&3;

    {
        const float* A = &g_qz[(by*128)*Dq];
        #pragma unroll
        for (int it = 0; it < 16; it++){
            int i4 = tid + it*256;
            int r = i4 >> 5, c4 = (i4 & 31)*4;
            float4 v = *(const float4*)&A[r*Dq + c4];
            *(uint4*)&qz_s[r*132+c4] = make_uint4(f2tf(v.x),f2tf(v.y),f2tf(v.z),f2tf(v.w));
        }
    }

    float Ua[2][8][4];
    #pragma unroll
    for (int s_ = 0; s_ < 2; s_++)
        #pragma unroll
        for (int i = 0; i < 8; i++){ Ua[s_][i][0]=0;Ua[s_][i][1]=0;Ua[s_][i][2]=0;Ua[s_][i][3]=0; }
    float s00=0.f, s01=0.f, s10=0.f, s11=0.f;

    int rA = wm*32 + g;
    int rB = rA + 16;

    int cu0 = (sp*VUNITS)/NSPLIT, cu1 = ((sp+1)*VUNITS)/NSPLIT;
    for (int ci = cu0; ci < cu1; ci++){
        __syncthreads();
        const float* Eb = &E[(size_t)(ci*64)*Dq];
        #pragma unroll
        for (int it = 0; it < 8; it++){
            int i4 = tid + it*256;
            int r = i4 >> 5, c4 = (i4 & 31)*4;
            float4 v = *(const float4*)&Eb[r*Dq + c4];
            *(uint4*)&E_s[r*132+c4] = make_uint4(f2tf(v.x),f2tf(v.y),f2tf(v.z),f2tf(v.w));
        }
        __syncthreads();

        // MMA1: L[32x32 per warp] = qz @ E^T
        float L[2][4][4];
        #pragma unroll
        for (int s_ = 0; s_ < 2; s_++)
            #pragma unroll
            for (int i = 0; i < 4; i++){ L[s_][i][0]=0;L[s_][i][1]=0;L[s_][i][2]=0;L[s_][i][3]=0; }
        const uint32_t* qr0 = &qz_s[rA*132 + q];
        const uint32_t* qr1 = &qz_s[rB*132 + q];
        #pragma unroll
        for (int ks = 0; ks < 16; ks++){
            int kb = ks*8;
            uint32_t a0[4] = { qr0[kb], qr0[kb + 8*132], qr0[kb+4], qr0[kb+4 + 8*132] };
            uint32_t a1[4] = { qr1[kb], qr1[kb + 8*132], qr1[kb+4], qr1[kb+4 + 8*132] };
            #pragma unroll
            for (int nt = 0; nt < 4; nt++){
                int nc = wn*32 + nt*8 + g;
                uint32_t b[2] = { E_s[nc*132 + kb + q], E_s[nc*132 + kb + q + 4] };
                mma8(L[0][nt], a0, b);
                mma8(L[1][nt], a1, b);
            }
        }

        // p = exp(L) (|L| <= ~6: qz rows are prob. distributions, E ~ N(0,1))
        #pragma unroll
        for (int nt = 0; nt < 4; nt++){
            int c0 = wn*32 + nt*8 + 2*q;
            float p0 = __expf(L[0][nt][0]), p1 = __expf(L[0][nt][1]);
            float p2 = __expf(L[0][nt][2]), p3 = __expf(L[0][nt][3]);
            s00 += p0 + p1; s01 += p2 + p3;
            p_s[rA*68 + c0] = f2tf(p0);     p_s[rA*68 + c0 + 1] = f2tf(p1);
            p_s[(rA+8)*68 + c0] = f2tf(p2); p_s[(rA+8)*68 + c0 + 1] = f2tf(p3);
            float u0 = __expf(L[1][nt][0]), u1 = __expf(L[1][nt][1]);
            float u2 = __expf(L[1][nt][2]), u3 = __expf(L[1][nt][3]);
            s10 += u0 + u1; s11 += u2 + u3;
            p_s[rB*68 + c0] = f2tf(u0);     p_s[rB*68 + c0 + 1] = f2tf(u1);
            p_s[(rB+8)*68 + c0] = f2tf(u2); p_s[(rB+8)*68 + c0 + 1] = f2tf(u3);
        }
        __syncthreads();

        // MMA2: Ua[32x128 per warp] += p @ E
        #pragma unroll
        for (int ks = 0; ks < 8; ks++){
            int kb = ks*8;
            uint32_t a0[4] = { p_s[rA*68 + kb + q],     p_s[(rA+8)*68 + kb + q],
                               p_s[rA*68 + kb + q + 4], p_s[(rA+8)*68 + kb + q + 4] };
            uint32_t a1[4] = { p_s[rB*68 + kb + q],     p_s[(rB+8)*68 + kb + q],
                               p_s[rB*68 + kb + q + 4], p_s[(rB+8)*68 + kb + q + 4] };
            #pragma unroll
            for (int nt2 = 0; nt2 < 8; nt2++){
                int nd = wn*64 + nt2*8 + g;
                uint32_t b[2] = { E_s[(kb+q)*132 + nd], E_s[(kb+q+4)*132 + nd] };
                mma8(Ua[0][nt2], a0, b);
                mma8(Ua[1][nt2], a1, b);
            }
        }
    }

    size_t base = ((size_t)sp*NROWS + by*128);
    #pragma unroll
    for (int s_ = 0; s_ < 2; s_++){
        int rlo = (s_ ? rB : rA), rhi = rlo + 8;
        #pragma unroll
        for (int nt2 = 0; nt2 < 8; nt2++){
            int col = wn*64 + nt2*8 + 2*q;
            *(float2*)&g_Um[(base + rlo)*Dq + col] = make_float2(Ua[s_][nt2][0], Ua[s_][nt2][1]);
            *(float2*)&g_Um[(base + rhi)*Dq + col] = make_float2(Ua[s_][nt2][2], Ua[s_][nt2][3]);
        }
    }
    #pragma unroll
    for (int o = 1; o <= 2; o <<= 1){
        s00 += __shfl_xor_sync(0xffffffffu, s00, o);
        s01 += __shfl_xor_sync(0xffffffffu, s01, o);
        s10 += __shfl_xor_sync(0xffffffffu, s10, o);
        s11 += __shfl_xor_sync(0xffffffffu, s11, o);
    }
    if (q == 0){
        wred[wn*128 + rA]     = s00;
        wred[wn*128 + rA + 8] = s01;
        wred[wn*128 + rB]     = s10;
        wred[wn*128 + rB + 8] = s11;
    }
    __syncthreads();
    if (tid < 128)
        g_srow[sp*NROWS + by*128 + tid] = wred[tid] + wred[128+tid];
}

// final logits: out[512,32000] = qz @ E^T — 128-row blocks, 32x32 warp tiles
#define LOGIT_SMEM ((QZW + EW)*4)
__global__ void __launch_bounds__(256,1) k_logits(const float* __restrict__ E, float* __restrict__ out){
    extern __shared__ uint32_t sh[];
    uint32_t* qz_s = sh;          // [128][132]
    uint32_t* E_s  = sh + QZW;    // [64][132]
    int tid = threadIdx.x;
    int bx = blockIdx.x, by = blockIdx.y;
    int warp = tid>>5, lane = tid&31;
    int wm = warp>>1, wn = warp&1;
    int g = lane>>2, q = lane&3;
    {
        const float* A = &g_qz[(by*128)*Dq];
        #pragma unroll
        for (int it = 0; it < 16; it++){
            int i4 = tid + it*256;
            int r = i4 >> 5, c4 = (i4 & 31)*4;
            float4 v = *(const float4*)&A[r*Dq + c4];
            *(uint4*)&qz_s[r*132+c4] = make_uint4(f2tf(v.x),f2tf(v.y),f2tf(v.z),f2tf(v.w));
        }
        const float* Eb = &E[(size_t)(bx*64)*Dq];
        #pragma unroll
        for (int it = 0; it < 8; it++){
            int i4 = tid + it*256;
            int r = i4 >> 5, c4 = (i4 & 31)*4;
            float4 e = *(const float4*)&Eb[r*Dq + c4];
            *(uint4*)&E_s[r*132+c4] = make_uint4(f2tf(e.x),f2tf(e.y),f2tf(e.z),f2tf(e.w));
        }
    }
    __syncthreads();
    int rA = wm*32 + g, rB = rA + 16;
    float L[2][4][4];
    #pragma unroll
    for (int s_ = 0; s_ < 2; s_++)
        #pragma unroll
        for (int i = 0; i < 4; i++){ L[s_][i][0]=0;L[s_][i][1]=0;L[s_][i][2]=0;L[s_][i][3]=0; }
    const uint32_t* qr0 = &qz_s[rA*132 + q];
    const uint32_t* qr1 = &qz_s[rB*132 + q];
    #pragma unroll
    for (int ks = 0; ks < 16; ks++){
        int kb = ks*8;
        uint32_t a0[4] = { qr0[kb], qr0[kb + 8*132], qr0[kb+4], qr0[kb+4 + 8*132] };
        uint32_t a1[4] = { qr1[kb], qr1[kb + 8*132], qr1[kb+4], qr1[kb+4 + 8*132] };
        #pragma unroll
        for (int nt = 0; nt < 4; nt++){
            int nc = wn*32 + nt*8 + g;
            uint32_t b[2] = { E_s[nc*132 + kb + q], E_s[nc*132 + kb + q + 4] };
            mma8(L[0][nt], a0, b);
            mma8(L[1][nt], a1, b);
        }
    }
    #pragma unroll
    for (int s_ = 0; s_ < 2; s_++){
        int rlo = by*128 + (s_ ? rB : rA), rhi = rlo + 8;
        #pragma unroll
        for (int nt = 0; nt < 4; nt++){
            int col = bx*64 + wn*32 + nt*8 + 2*q;
            *(float2*)&out[(size_t)rlo*Vq + col] = make_float2(L[s_][nt][0], L[s_][nt][1]);
            *(float2*)&out[(size_t)rhi*Vq + col] = make_float2(L[s_][nt][2], L[s_][nt][3]);
        }
    }
}

// ---------------- generic strided batched tf32 GEMM ----------------
// M=128 (full), N-tile 64, K=128. 8 warps = 4 row-slabs(32) x 2 col(32).
// aMode/bMode: 0 = scalar mn-fast, 1 = scalar k-fast, 2 = float4 contiguous,
// bMode 3 = T-packed (a,c) columns: addr = (n>>3)*DHq + k*Hq + (n&7).
struct GCfg {
    const float* A; const float* B; float* C;
    int sAi, sAk, sBk, sBj, sCi, sCj;
    int b3, b2;
    int aB1, aB2, aB3, bB1, bB2, bB3, cB1, cB2, cB3;
    int aMode, bMode;
};

#define GEMM_SMEM ((128*132 + 128*68)*4)   // 102400 B

__device__ __forceinline__ void gemm_body(const GCfg& c, int bz, uint32_t* dsh){
    uint32_t* As = dsh;             // [128][132]  m-major
    uint32_t* Bs = dsh + 128*132;   // [128][68]   k-major

    int i3 = bz % c.b3; int t_ = bz / c.b3; int i2 = t_ % c.b2; int i1 = t_ / c.b2;
    const float* A  = c.A + (size_t)i1*c.aB1 + (size_t)i2*c.aB2 + (size_t)i3*c.aB3;
    const float* Bm = c.B + (size_t)i1*c.bB1 + (size_t)i2*c.bB2 + (size_t)i3*c.bB3;
    float* C        = c.C + (size_t)i1*c.cB1 + (size_t)i2*c.cB2 + (size_t)i3*c.cB3;
    int n0 = blockIdx.x*64;

    int tid = threadIdx.x;
    int warp = tid>>5, lane = tid&31;
    int wm = warp>>1, wn = warp&1;
    int g = lane>>2, q = lane&3;

    // ---- stage A: 128 x 128 ----
    if (c.aMode == 2){
        #pragma unroll
        for (int it = 0; it < 16; it++){
            int i4 = tid + it*256;
            int r = i4 >> 5, k4 = (i4 & 31)*4;
            float4 v = *(const float4*)&A[(size_t)r*c.sAi + k4];
            *(uint4*)&As[r*132 + k4] = make_uint4(f2tf(v.x),f2tf(v.y),f2tf(v.z),f2tf(v.w));
        }
    } else if (c.aMode == 1){
        #pragma unroll
        for (int it = 0; it < 64; it++){
            int idx = tid + it*256;
            int kk = idx & 127, mn = idx >> 7;
            As[mn*132 + kk] = f2tf(A[(size_t)mn*c.sAi + (size_t)kk*c.sAk]);
        }
    } else {
        #pragma unroll
        for (int it = 0; it < 64; it++){
            int idx = tid + it*256;
            int mn = idx & 127, kk = idx >> 7;
            As[mn*132 + kk] = f2tf(A[(size_t)mn*c.sAi + (size_t)kk*c.sAk]);
        }
    }
    // ---- stage B: 128k x 64n ----
    if (c.bMode == 2){
        #pragma unroll
        for (int it = 0; it < 8; it++){
            int i4 = tid + it*256;
            int kk = i4 >> 4, n4 = (i4 & 15)*4;
            float4 v = *(const float4*)&Bm[(size_t)kk*c.sBk + (n0+n4)];
            *(uint4*)&Bs[kk*68 + n4] = make_uint4(f2tf(v.x),f2tf(v.y),f2tf(v.z),f2tf(v.w));
        }
    } else if (c.bMode == 3){
        // t2 build: B[k=b][n=(a*8+c)] = T[(n>>3)*DHq + b*Hq + (n&7)]
        #pragma unroll
        for (int it = 0; it < 32; it++){
            int idx = tid + it*256;
            int mn = idx & 63, kk = idx >> 6;
            int n = n0 + mn;
            Bs[kk*68 + mn] = f2tf(Bm[(size_t)(n>>3)*DHq + (size_t)kk*Hq + (n&7)]);
        }
    } else if (c.bMode == 1){
        #pragma unroll
        for (int it = 0; it < 32; it++){
            int idx = tid + it*256;
            int kk = idx & 127, mn = idx >> 7;
            Bs[kk*68 + mn] = f2tf(Bm[(size_t)kk*c.sBk + (size_t)(n0+mn)*c.sBj]);
        }
    } else {
        #pragma unroll
        for (int it = 0; it < 32; it++){
            int idx = tid + it*256;
            int mn = idx & 63, kk = idx >> 6;
            Bs[kk*68 + mn] = f2tf(Bm[(size_t)kk*c.sBk + (size_t)(n0+mn)*c.sBj]);
        }
    }
    __syncthreads();

    float acc[2][4][4];
    #pragma unroll
    for (int s_ = 0; s_ < 2; s_++)
        #pragma unroll
        for (int i = 0; i < 4; i++){ acc[s_][i][0]=0;acc[s_][i][1]=0;acc[s_][i][2]=0;acc[s_][i][3]=0; }

    int rA = wm*32 + g, rB = rA + 16;
    const uint32_t* a0p = &As[rA*132 + q];
    const uint32_t* a1p = &As[rB*132 + q];
    #pragma unroll
    for (int ks = 0; ks < 16; ks++){
        int kb = ks*8;
        uint32_t a0[4] = { a0p[kb], a0p[kb + 8*132], a0p[kb+4], a0p[kb+4 + 8*132] };
        uint32_t a1[4] = { a1p[kb], a1p[kb + 8*132], a1p[kb+4], a1p[kb+4 + 8*132] };
        #pragma unroll
        for (int nt = 0; nt < 4; nt++){
            int n = wn*32 + nt*8 + g;
            uint32_t b[2] = { Bs[(kb+q)*68 + n], Bs[(kb+q+4)*68 + n] };
            mma8(acc[0][nt], a0, b);
            mma8(acc[1][nt], a1, b);
        }
    }

    #pragma unroll
    for (int s_ = 0; s_ < 2; s_++){
        int rlo = (s_ ? rB : rA), rhi = rlo + 8;
        #pragma unroll
        for (int nt = 0; nt < 4; nt++){
            int c0 = n0 + wn*32 + nt*8 + 2*q;
            C[(size_t)rlo*c.sCi + (size_t)(c0  )*c.sCj] = acc[s_][nt][0];
            C[(size_t)rlo*c.sCi + (size_t)(c0+1)*c.sCj] = acc[s_][nt][1];
            C[(size_t)rhi*c.sCi + (size_t)(c0  )*c.sCj] = acc[s_][nt][2];
            C[(size_t)rhi*c.sCi + (size_t)(c0+1)*c.sCj] = acc[s_][nt][3];
        }
    }
}

__global__ void __launch_bounds__(256,2) k_gemm_tf(GCfg c){
    extern __shared__ uint32_t dsh[];
    gemm_body(c, blockIdx.z, dsh);
}

__global__ void __launch_bounds__(256,2) k_gemm_dual(GCfg c0, GCfg c1, int zsplit){
    extern __shared__ uint32_t dsh[];
    int bz = blockIdx.z;
    if (bz < zsplit) gemm_body(c0, bz, dsh);
    else             gemm_body(c1, bz - zsplit, dsh);
}

// ---------------- host ----------------
extern "C" void kernel_launch(void* const* d_in, const int* in_sizes, int n_in,
                              void* d_out, int out_size){
    const float* x      = (const float*)d_in[0];
    const int*   mask   = (const int*)  d_in[1];
    const float* E      = (const float*)d_in[2];
    const int*   m_mask = (const int*)  d_in[3];
    const float* T      = (const float*)d_in[4];
    float* out = (float*)d_out;

    cudaFuncSetAttribute(k_flash,    cudaFuncAttributeMaxDynamicSharedMemorySize, FLASH_SMEM);
    cudaFuncSetAttribute(k_logits,   cudaFuncAttributeMaxDynamicSharedMemorySize, LOGIT_SMEM);
    cudaFuncSetAttribute(k_gemm_tf,  cudaFuncAttributeMaxDynamicSharedMemorySize, GEMM_SMEM);
    cudaFuncSetAttribute(k_gemm_dual,cudaFuncAttributeMaxDynamicSharedMemorySize, GEMM_SMEM);

    void* qp;
    float *Pqz,*Pt1,*Pt2,*PF,*PHm,*PGp;
    cudaGetSymbolAddress(&qp, g_qz);    Pqz = (float*)qp;
    cudaGetSymbolAddress(&qp, g_t1);    Pt1 = (float*)qp;
    cudaGetSymbolAddress(&qp, g_t2);    Pt2 = (float*)qp;
    cudaGetSymbolAddress(&qp, g_F);     PF  = (float*)qp;
    cudaGetSymbolAddress(&qp, g_Hm);    PHm = (float*)qp;
    cudaGetSymbolAddress(&qp, g_Gpart); PGp = (float*)qp;

    // --- GEMM configs (M=128 full tile, N-tile 64) ---
    // t1[z,k,i,(b*H+c)] = sum_a qz[z,i,a] T[k,a,(b,c)]
    GCfg cT1 = { Pqz, T, Pt1,
        Dq,1,  DHq,1,  DHq,1,
        1,2,
        Lq*Dq,0,0,   0,Dq*DHq,0,   2*Lq*DHq,Lq*DHq,0,
        2,2 };
    // t2[z,k,j,(a*H+c)] = sum_b qz[z,j,b] T[k,a,b,c]  (bMode 3: packed T columns)
    GCfg cT2 = { Pqz, T, Pt2,
        Dq,1,  Hq,1,  DHq,1,
        1,2,
        Lq*Dq,0,0,   0,Dq*DHq,0,   2*Lq*DHq,Lq*DHq,0,
        2,3 };
    // F[z,k,c,i,j] = sum_b t1[z,k,i,(b,c)] qz[z,j,b]
    GCfg cF = { Pt1, Pqz, PF,
        DHq,Hq,  1,Dq,  Lq,1,
        8,2,
        2*Lq*DHq,Lq*DHq,1,  Lq*Dq,0,0,  2*Hq*Lq*Lq,Hq*Lq*Lq,Lq*Lq,
        1,1 };
    // G1 parts[(k*8+c)][z,i,a] = sum_j Hm[k,z,c,i,j] t2[z,k,j,(a*H+c)]
    GCfg cG1 = { PHm, Pt2, PGp,
        Lq,1,  DHq,Hq,  Dq,1,
        8,2,
        Hq*Lq*Lq, Bq*Hq*Lq*Lq, Lq*Lq,
        2*Lq*DHq, Lq*DHq,      1,
        Lq*Dq,    8*NROWS*Dq,  NROWS*Dq,
        2,0 };
    // G2 parts[16+(k*8+c)][z,j,b] = sum_i Hm[k,z,c,i,j] t1[z,k,i,(b*H+c)]
    GCfg cG2 = { PHm, Pt1, PGp + (size_t)16*NROWS*Dq,
        1,Lq,  DHq,Hq,  Dq,1,
        8,2,
        Hq*Lq*Lq, Bq*Hq*Lq*Lq, Lq*Lq,
        2*Lq*DHq, Lq*DHq,      1,
        Lq*Dq,    8*NROWS*Dq,  NROWS*Dq,
        0,0 };

    // preprocessing: meanE, then initial compose+softmax
    k_meanE_part<<<128,128>>>(E);
    k_meanE_red<<<1,128>>>();
    k_fuse_row<<<NROWS, 128>>>(mask, x, m_mask, 0, 0);

    for (int t = 0; t < 4; t++){
        // t1 and t2 both depend only on qz — one dual launch (256 blocks)
        k_gemm_dual<<<dim3(16,1,16), 256, GEMM_SMEM>>>(cT1, cT2, 8);
        k_gemm_tf<<<dim3(2,1,64),    256, GEMM_SMEM>>>(cF);
        k_hsoftmax<<<Bq*Hq*Lq, 128>>>(mask);
        // G1 and G2 both depend on (Hm, t1/t2) — one dual launch
        k_gemm_dual<<<dim3(2,1,128), 256, GEMM_SMEM>>>(cG1, cG2, 64);

        if (t > 0){
            k_flash<<<dim3(NSPLIT, 4), 256, FLASH_SMEM>>>(E);
        }
        k_fuse_row<<<NROWS, 128>>>(mask, x, m_mask, (t > 0) ? 1 : 0, 1);

        if (t == 3){
            k_logits<<<dim3(Vq/64, 4), 256, LOGIT_SMEM>>>(E, out);
        }
    }
}